// round 10
// baseline (speedup 1.0000x reference)
#include <cuda_runtime.h>
#include <cuda_bf16.h>
#include <math.h>

#define Nn   16000
#define Ee   48000
#define Ff   32000
#define Dd   64
#define Bb   32
#define Gg   32
#define HIDN 256
#define NCc  10

#define DSLICE 4
#define NSLICE (Dd / DSLICE)          // 16
#define CHUNKS 20
#define M_TOTAL (Nn + Ee + Ff)        // 96000
#define ITEMS_PER_CHUNK ((M_TOTAL + CHUNKS - 1) / CHUNKS)  // 4800

#define C_HALF 3.2258064516f          // 0.5 * SCALE * (2/31)

#define PSTRIDE 5                      // padded bin stride: bank = (5b+dloc) mod 32
#define SIGP_SZ (Gg * Bb * PSTRIDE)            // 5120 floats
#define STEPP_SZ (Gg * (Bb + 1) * PSTRIDE)     // 5280 floats

#define KC 8
#define JG 32
#define FPAD 4
#define FSTRIDE (256 + FPAD)

// scratch (device globals: no allocations allowed)
__device__ float d_nh[Nn * Dd];                    // 4 MB: per-node heights
__device__ float d_sig[Gg * Bb * Dd];              // windowed-sigmoid partials
__device__ float d_step[Gg * (Bb + 1) * Dd];       // step deltas
__device__ float d_h[Gg * HIDN];                   // hidden pre-activations

// fused: zero accumulators + seed d_h with b1 + compute node heights
__global__ void init_kernel(const float* __restrict__ x, const float* __restrict__ nw,
                            const float* __restrict__ v, const float* __restrict__ b1) {
    int i = blockIdx.x * blockDim.x + threadIdx.x;
    if (i < Gg * Bb * Dd) d_sig[i] = 0.f;
    if (i < Gg * (Bb + 1) * Dd) d_step[i] = 0.f;
    if (i < Gg * HIDN) d_h[i] = b1[i & (HIDN - 1)];
    if (i >= Nn * (Dd / 4)) return;
    int n = i >> 4, q = i & 15;
    float w = nw[n];
    float x0 = x[n * 3 + 0] * w, x1 = x[n * 3 + 1] * w, x2 = x[n * 3 + 2] * w;
    float4 v0 = ((const float4*)(v))[q];
    float4 v1 = ((const float4*)(v + Dd))[q];
    float4 v2 = ((const float4*)(v + 2 * Dd))[q];
    float4 r;
    r.x = x0 * v0.x + x1 * v1.x + x2 * v2.x;
    r.y = x0 * v0.y + x1 * v1.y + x2 * v2.y;
    r.z = x0 * v0.z + x1 * v1.z + x2 * v2.z;
    r.w = x0 * v0.w + x1 * v1.w + x2 * v2.w;
    ((float4*)d_nh)[i] = r;
}

__device__ __forceinline__ float fast_tanh(float u) {
    float r;
    asm("tanh.approx.f32 %0, %1;" : "=f"(r) : "f"(u));
    return r;
}

__global__ void __launch_bounds__(512) ecc_kernel(
    const float* __restrict__ ew, const float* __restrict__ fw,
    const int* __restrict__ eidx, const int* __restrict__ fidx,
    const int* __restrict__ batch)
{
    __shared__ float s_sig[SIGP_SZ];            // 20 KB (padded stride 5)
    __shared__ float s_step[STEPP_SZ];          // 21 KB (padded stride 5)
    const int tid = threadIdx.x;
    for (int i = tid; i < SIGP_SZ; i += 512) s_sig[i] = 0.f;
    for (int i = tid; i < STEPP_SZ; i += 512) s_step[i] = 0.f;
    __syncthreads();

    const int slice = blockIdx.y;
    const int dloc  = tid & (DSLICE - 1);
    const int dglob = slice * DSLICE + dloc;
    const int itemoff = tid >> 2;                      // 0..127
    const int base = blockIdx.x * ITEMS_PER_CHUNK;
    const int iend = min(M_TOTAL, base + ITEMS_PER_CHUNK);

    const float inv_dl = 31.f * 0.5f;

    for (int id = base + itemoff; id < iend; id += 128) {
        float h, sign; int g;
        if (id < Nn) {
            h = d_nh[id * Dd + dglob];
            g = batch[id];
            sign = 1.f;
        } else if (id < Nn + Ee) {
            int e = id - Nn;
            int a = eidx[e];
            int b = eidx[Ee + e];
            h = fmaxf(d_nh[a * Dd + dglob], d_nh[b * Dd + dglob]) * ew[e];
            g = batch[a];
            sign = -1.f;
        } else {
            int f = id - Nn - Ee;
            int a = fidx[f];
            int b = fidx[Ff + f];
            int c = fidx[2 * Ff + f];
            h = fmaxf(fmaxf(d_nh[a * Dd + dglob], d_nh[b * Dd + dglob]),
                      d_nh[c * Dd + dglob]) * fw[f];
            g = batch[a];
            sign = 1.f;
        }

        // 3-bump window centered on nearest bump: r-1, r, r+1 (max dist 1.5)
        float t = fmaf(h, inv_dl, inv_dl);
        float rff = floorf(t + 0.5f);
        int rr = (int)rff;
        int b_end = min(max(rr + 2, 0), Bb);

        float shalf = 0.5f * sign;
        float u = (rff - 1.0f - t) * C_HALF;
        float* sb = &s_sig[g * (Bb * PSTRIDE) + dloc];
        #pragma unroll
        for (int j = 0; j < 3; ++j) {
            int b = rr - 1 + j;
            float val = fmaf(shalf, fast_tanh(u), shalf);
            if ((unsigned)b < (unsigned)Bb) {
                atomicAdd(sb + b * PSTRIDE, val);
            }
            u += C_HALF;
        }
        atomicAdd(&s_step[(g * (Bb + 1) + b_end) * PSTRIDE + dloc], sign);
    }
    __syncthreads();

    // flush block partials to global (un-pad), skipping zeros
    for (int i = tid; i < Gg * Bb * DSLICE; i += 512) {
        int row = i >> 2, d0 = i & 3;                  // row = g*32+b
        float vsum = s_sig[row * PSTRIDE + d0];
        if (vsum != 0.f)
            atomicAdd(&d_sig[row * Dd + slice * DSLICE + d0], vsum);
    }
    for (int i = tid; i < Gg * (Bb + 1) * DSLICE; i += 512) {
        int row = i >> 2, d0 = i & 3;                  // row = g*33+b
        float vsum = s_step[row * PSTRIDE + d0];
        if (vsum != 0.f)
            atomicAdd(&d_step[row * Dd + slice * DSLICE + d0], vsum);
    }
}

// prefix over bumps: flat[g][b][d] = sig + running step
__global__ void combine_kernel(float* __restrict__ flat) {
    int g = blockIdx.x;
    int d = threadIdx.x;                // 64 threads
    float run = 0.f;
    const float* stp = &d_step[g * (Bb + 1) * Dd + d];
    const float* sgp = &d_sig[g * Bb * Dd + d];
    float* fp = &flat[g * Bb * Dd + d];
    #pragma unroll 8
    for (int b = 0; b < Bb; ++b) {
        run += stp[b * Dd];
        fp[b * Dd] = sgp[b * Dd] + run;
    }
}

// first GEMM layer, split-K over bump chunks
__global__ void __launch_bounds__(256) mlp1_kernel(
    const float* __restrict__ W1, const float* __restrict__ flat)
{
    __shared__ float s_f[Gg * FSTRIDE];
    __shared__ float s_w[8 * 256];
    const int tid = threadIdx.x;
    const int kc = blockIdx.x;
    const int jg = blockIdx.y;
    const int bb0 = kc * 4;

    #pragma unroll
    for (int r = 0; r < 8; ++r) {
        int idx = tid + r * 256;
        int g = idx >> 6;
        int c4 = idx & 63;
        float4 val = *(const float4*)&flat[(size_t)(g * Bb + bb0) * Dd + c4 * 4];
        *(float4*)&s_f[g * FSTRIDE + c4 * 4] = val;
    }
    {
        const int koff = bb0 * Dd;
        #pragma unroll
        for (int r = 0; r < 2; ++r) {
            int idx = tid + r * 256;
            int row = idx >> 6, col = (idx & 63) << 2;
            ((float4*)s_w)[idx] = *(const float4*)&W1[(size_t)(jg * 8 + row) * (Bb * Dd) + koff + col];
        }
    }
    __syncthreads();

    const int j = tid >> 5;
    const int g = tid & 31;
    const float4* wrow = (const float4*)&s_w[j * 256];
    const float* frow = &s_f[g * FSTRIDE];
    float acc = 0.f;
    #pragma unroll 8
    for (int k4 = 0; k4 < 64; ++k4) {
        float4 w = wrow[k4];
        float4 f = *(const float4*)&frow[k4 * 4];
        acc = fmaf(w.x, f.x, acc);
        acc = fmaf(w.y, f.y, acc);
        acc = fmaf(w.z, f.z, acc);
        acc = fmaf(w.w, f.w, acc);
    }
    atomicAdd(&d_h[g * HIDN + jg * 8 + j], acc);
}

// relu + second layer: one warp per output class
__global__ void __launch_bounds__(320) mlp2_kernel(
    const float* __restrict__ W2, const float* __restrict__ b2,
    float* __restrict__ logits)
{
    const int g = blockIdx.x;
    const int w = threadIdx.x >> 5;
    const int lane = threadIdx.x & 31;
    float acc = 0.f;
    #pragma unroll
    for (int k8 = 0; k8 < HIDN / 32; ++k8) {
        int k = k8 * 32 + lane;
        float hv = fmaxf(d_h[g * HIDN + k], 0.f);
        acc = fmaf(hv, W2[w * HIDN + k], acc);
    }
    #pragma unroll
    for (int off = 16; off; off >>= 1)
        acc += __shfl_xor_sync(0xffffffffu, acc, off);
    if (lane == 0) logits[g * NCc + w] = b2[w] + acc;
}

extern "C" void kernel_launch(void* const* d_in, const int* in_sizes, int n_in,
                              void* d_out, int out_size) {
    const float* x   = (const float*)d_in[0];
    const float* nw  = (const float*)d_in[1];
    const float* ew  = (const float*)d_in[2];
    const float* fw  = (const float*)d_in[3];
    const float* v   = (const float*)d_in[4];
    const float* W1  = (const float*)d_in[5];
    const float* b1  = (const float*)d_in[6];
    const float* W2  = (const float*)d_in[7];
    const float* b2  = (const float*)d_in[8];
    const int* eidx  = (const int*)d_in[9];
    const int* fidx  = (const int*)d_in[10];
    const int* batch = (const int*)d_in[11];

    float* out = (float*)d_out;
    float* logits = out;                 // [32, 10]
    float* flat   = out + Gg * NCc;      // [32, 2048]

    init_kernel<<<(Nn * (Dd / 4) + 255) / 256, 256>>>(x, nw, v, b1);
    dim3 grid(CHUNKS, NSLICE);
    ecc_kernel<<<grid, 512>>>(ew, fw, eidx, fidx, batch);
    combine_kernel<<<Gg, Dd>>>(flat);
    dim3 mgrid(KC, JG);
    mlp1_kernel<<<mgrid, 256>>>(W1, flat);
    mlp2_kernel<<<Gg, 320>>>(W2, b2, logits);
}

// round 11
// speedup vs baseline: 1.1479x; 1.1479x over previous
#include <cuda_runtime.h>
#include <cuda_bf16.h>
#include <math.h>

#define Nn   16000
#define Ee   48000
#define Ff   32000
#define Dd   64
#define Bb   32
#define Gg   32
#define HIDN 256
#define NCc  10

#define DSL 8                          // dirs per block slice (lane-owned)
#define NSL (Dd / DSL)                 // 8 slices
#define CHUNKS 40
#define M_TOTAL (Nn + Ee + Ff)         // 96000
#define ITEMS_PER_CHUNK ((M_TOTAL + CHUNKS - 1) / CHUNKS)  // 2400

#define C_HALF 3.2258064516f           // 0.5 * SCALE * (2/31)

#define KC 8
#define JG 32
#define FPAD 4
#define FSTRIDE (256 + FPAD)

// scratch (device globals: no allocations allowed)
__device__ float d_nh[Nn * Dd];                    // 4 MB: per-node heights
__device__ float d_sig[Gg * Bb * Dd];              // windowed-sigmoid partials
__device__ float d_step[Gg * (Bb + 1) * Dd];       // step deltas
__device__ float d_h[Gg * HIDN];                   // hidden pre-activations

// fused: zero accumulators + seed d_h with b1 + compute node heights
__global__ void init_kernel(const float* __restrict__ x, const float* __restrict__ nw,
                            const float* __restrict__ v, const float* __restrict__ b1) {
    int i = blockIdx.x * blockDim.x + threadIdx.x;
    if (i < Gg * Bb * Dd) d_sig[i] = 0.f;
    if (i < Gg * (Bb + 1) * Dd) d_step[i] = 0.f;
    if (i < Gg * HIDN) d_h[i] = b1[i & (HIDN - 1)];
    if (i >= Nn * (Dd / 4)) return;
    int n = i >> 4, q = i & 15;
    float w = nw[n];
    float x0 = x[n * 3 + 0] * w, x1 = x[n * 3 + 1] * w, x2 = x[n * 3 + 2] * w;
    float4 v0 = ((const float4*)(v))[q];
    float4 v1 = ((const float4*)(v + Dd))[q];
    float4 v2 = ((const float4*)(v + 2 * Dd))[q];
    float4 r;
    r.x = x0 * v0.x + x1 * v1.x + x2 * v2.x;
    r.y = x0 * v0.y + x1 * v1.y + x2 * v2.y;
    r.z = x0 * v0.z + x1 * v1.z + x2 * v2.z;
    r.w = x0 * v0.w + x1 * v1.w + x2 * v2.w;
    ((float4*)d_nh)[i] = r;
}

__device__ __forceinline__ float fast_tanh(float u) {
    float r;
    asm("tanh.approx.f32 %0, %1;" : "=f"(r) : "f"(u));
    return r;
}

// warp = 4 items x 8 dirs; lane owns a direction -> no same-address ATOMS within warp
__global__ void __launch_bounds__(256) ecc_kernel(
    const float* __restrict__ ew, const float* __restrict__ fw,
    const int* __restrict__ eidx, const int* __restrict__ fidx,
    const int* __restrict__ batch)
{
    __shared__ float s_sig[Gg * Bb * DSL];             // 32 KB
    __shared__ float s_step[Gg * (Bb + 1) * DSL];      // 33 KB
    const int tid = threadIdx.x;
    for (int i = tid; i < Gg * Bb * DSL; i += 256) s_sig[i] = 0.f;
    for (int i = tid; i < Gg * (Bb + 1) * DSL; i += 256) s_step[i] = 0.f;
    __syncthreads();

    const int slice = blockIdx.y;                      // 0..7
    const int lane  = tid & 31;
    const int wid   = tid >> 5;                        // 0..7
    const int dloc  = lane & (DSL - 1);                // 0..7
    const int isub  = lane >> 3;                       // 0..3
    const int dglob = slice * DSL + dloc;
    const int itemoff = wid * 4 + isub;                // 0..31
    const int base = blockIdx.x * ITEMS_PER_CHUNK;
    const int iend = min(M_TOTAL, base + ITEMS_PER_CHUNK);

    const float inv_dl = 31.f * 0.5f;

    for (int id = base + itemoff; id < iend; id += 32) {
        float h, sign; int g;
        if (id < Nn) {
            h = d_nh[id * Dd + dglob];
            g = batch[id];
            sign = 1.f;
        } else if (id < Nn + Ee) {
            int e = id - Nn;
            int a = eidx[e];
            int b = eidx[Ee + e];
            h = fmaxf(d_nh[a * Dd + dglob], d_nh[b * Dd + dglob]) * ew[e];
            g = batch[a];
            sign = -1.f;
        } else {
            int f = id - Nn - Ee;
            int a = fidx[f];
            int b = fidx[Ff + f];
            int c = fidx[2 * Ff + f];
            h = fmaxf(fmaxf(d_nh[a * Dd + dglob], d_nh[b * Dd + dglob]),
                      d_nh[c * Dd + dglob]) * fw[f];
            g = batch[a];
            sign = 1.f;
        }

        // 3-bump window centered on nearest bump: r-1, r, r+1 (max dist 1.5)
        float t = fmaf(h, inv_dl, inv_dl);
        float rff = floorf(t + 0.5f);
        int rr = (int)rff;
        int b_end = min(max(rr + 2, 0), Bb);

        float shalf = 0.5f * sign;
        float u = (rff - 1.0f - t) * C_HALF;
        float* sb = &s_sig[(g * Bb) * DSL + dloc];
        #pragma unroll
        for (int j = 0; j < 3; ++j) {
            int b = rr - 1 + j;
            float val = fmaf(shalf, fast_tanh(u), shalf);
            if ((unsigned)b < (unsigned)Bb) {
                atomicAdd(sb + b * DSL, val);
            }
            u += C_HALF;
        }
        atomicAdd(&s_step[(g * (Bb + 1) + b_end) * DSL + dloc], sign);
    }
    __syncthreads();

    // flush block partials to global, skipping zeros
    for (int i = tid; i < Gg * Bb * DSL; i += 256) {
        float vsum = s_sig[i];
        if (vsum != 0.f) {
            int row = i >> 3, d0 = i & 7;              // row = g*32+b
            atomicAdd(&d_sig[row * Dd + slice * DSL + d0], vsum);
        }
    }
    for (int i = tid; i < Gg * (Bb + 1) * DSL; i += 256) {
        float vsum = s_step[i];
        if (vsum != 0.f) {
            int row = i >> 3, d0 = i & 7;              // row = g*33+b
            atomicAdd(&d_step[row * Dd + slice * DSL + d0], vsum);
        }
    }
}

// prefix over bumps: flat[g][b][d] = sig + running step
__global__ void combine_kernel(float* __restrict__ flat) {
    int g = blockIdx.x;
    int d = threadIdx.x;                // 64 threads
    float run = 0.f;
    const float* stp = &d_step[g * (Bb + 1) * Dd + d];
    const float* sgp = &d_sig[g * Bb * Dd + d];
    float* fp = &flat[g * Bb * Dd + d];
    #pragma unroll 8
    for (int b = 0; b < Bb; ++b) {
        run += stp[b * Dd];
        fp[b * Dd] = sgp[b * Dd] + run;
    }
}

// first GEMM layer, split-K over bump chunks
__global__ void __launch_bounds__(256) mlp1_kernel(
    const float* __restrict__ W1, const float* __restrict__ flat)
{
    __shared__ float s_f[Gg * FSTRIDE];
    __shared__ float s_w[8 * 256];
    const int tid = threadIdx.x;
    const int kc = blockIdx.x;
    const int jg = blockIdx.y;
    const int bb0 = kc * 4;

    #pragma unroll
    for (int r = 0; r < 8; ++r) {
        int idx = tid + r * 256;
        int g = idx >> 6;
        int c4 = idx & 63;
        float4 val = *(const float4*)&flat[(size_t)(g * Bb + bb0) * Dd + c4 * 4];
        *(float4*)&s_f[g * FSTRIDE + c4 * 4] = val;
    }
    {
        const int koff = bb0 * Dd;
        #pragma unroll
        for (int r = 0; r < 2; ++r) {
            int idx = tid + r * 256;
            int row = idx >> 6, col = (idx & 63) << 2;
            ((float4*)s_w)[idx] = *(const float4*)&W1[(size_t)(jg * 8 + row) * (Bb * Dd) + koff + col];
        }
    }
    __syncthreads();

    const int j = tid >> 5;
    const int g = tid & 31;
    const float4* wrow = (const float4*)&s_w[j * 256];
    const float* frow = &s_f[g * FSTRIDE];
    float acc = 0.f;
    #pragma unroll 8
    for (int k4 = 0; k4 < 64; ++k4) {
        float4 w = wrow[k4];
        float4 f = *(const float4*)&frow[k4 * 4];
        acc = fmaf(w.x, f.x, acc);
        acc = fmaf(w.y, f.y, acc);
        acc = fmaf(w.z, f.z, acc);
        acc = fmaf(w.w, f.w, acc);
    }
    atomicAdd(&d_h[g * HIDN + jg * 8 + j], acc);
}

// relu + second layer: one warp per output class
__global__ void __launch_bounds__(320) mlp2_kernel(
    const float* __restrict__ W2, const float* __restrict__ b2,
    float* __restrict__ logits)
{
    const int g = blockIdx.x;
    const int w = threadIdx.x >> 5;
    const int lane = threadIdx.x & 31;
    float acc = 0.f;
    #pragma unroll
    for (int k8 = 0; k8 < HIDN / 32; ++k8) {
        int k = k8 * 32 + lane;
        float hv = fmaxf(d_h[g * HIDN + k], 0.f);
        acc = fmaf(hv, W2[w * HIDN + k], acc);
    }
    #pragma unroll
    for (int off = 16; off; off >>= 1)
        acc += __shfl_xor_sync(0xffffffffu, acc, off);
    if (lane == 0) logits[g * NCc + w] = b2[w] + acc;
}

extern "C" void kernel_launch(void* const* d_in, const int* in_sizes, int n_in,
                              void* d_out, int out_size) {
    const float* x   = (const float*)d_in[0];
    const float* nw  = (const float*)d_in[1];
    const float* ew  = (const float*)d_in[2];
    const float* fw  = (const float*)d_in[3];
    const float* v   = (const float*)d_in[4];
    const float* W1  = (const float*)d_in[5];
    const float* b1  = (const float*)d_in[6];
    const float* W2  = (const float*)d_in[7];
    const float* b2  = (const float*)d_in[8];
    const int* eidx  = (const int*)d_in[9];
    const int* fidx  = (const int*)d_in[10];
    const int* batch = (const int*)d_in[11];

    float* out = (float*)d_out;
    float* logits = out;                 // [32, 10]
    float* flat   = out + Gg * NCc;      // [32, 2048]

    init_kernel<<<(Nn * (Dd / 4) + 255) / 256, 256>>>(x, nw, v, b1);
    dim3 grid(CHUNKS, NSL);
    ecc_kernel<<<grid, 256>>>(ew, fw, eidx, fidx, batch);
    combine_kernel<<<Gg, Dd>>>(flat);
    dim3 mgrid(KC, JG);
    mlp1_kernel<<<mgrid, 256>>>(W1, flat);
    mlp2_kernel<<<Gg, 320>>>(W2, b2, logits);
}